// round 14
// baseline (speedup 1.0000x reference)
#include <cuda_runtime.h>

// LS_loss: SINGLE persistent-wave kernel with in-kernel software grid-sync.
//
// Shapes: input, img_mean : (32, 4, 512, 512) fp32, contiguous.
// 128 channels x 262144 floats (= 65536 float4 each).
//
// Per channel (N = 262144):
//   Hea = 0.5*(1+tanh(x/0.05))
//   A = sum(Hea), B1 = sum(Hea*img), S = sum(img), Q = sum(img^2)
//   c1 = B1/(A+eps), c2 = (S-B1)/(N-A+eps)
//   chan = Q - 2*(c1*B1 + c2*(S-B1)) + c1^2*A + c2^2*(N-A)
//   out  = sum_chan / (B*C*H*W)
//
// Structure:
//  - 1024 blocks x 128 threads, __launch_bounds__(128,8): <=64 regs ->
//    8 blocks/SM -> capacity 148*8=1184 >= 1024: the WHOLE grid is resident
//    in one wave, so an in-kernel spin (block 0 only) cannot deadlock, and
//    ncu's single-kernel replay runs all blocks concurrently (safe).
//  - block b: channel ch=b>>3, sub=b&7. 16 tiles of 512 float4 interleaved
//    across the channel (tile ids sub+8k); per tile 8 front-batched LDG.128.
//  - block partial -> g_partials[b]; fence; arrive on g_ctr. Non-zero blocks
//    EXIT immediately (no spin). 1024th arriver resets g_ctr and increments
//    monotonic g_flag. Block 0 alone spins for g_flag to leave its entry
//    value, then finalizes: thread t = channel t reads its 8 partials,
//    closed form, deterministic 128-lane reduce, writes out[0].
//  - Replay-safe: g_ctr self-resets each launch; g_flag is monotonic and
//    block 0 compares against a value read before its own arrival (which
//    must precede the flip). All reduction orders fixed -> deterministic.

#define N_PER_CH    262144
#define F4_PER_CH   65536
#define SUBS        8                 // blocks per channel
#define NBLOCKS     (128 * SUBS)      // 1024
#define THREADS     128
#define TILES_PER_BLK 16
#define TILE_F4     512               // float4 per tile
#define GRP         4                 // float4 per thread per tile
#define LS_EPS      1e-4f
#define INV_EPISON  20.0f

static __device__ float4 g_partials[NBLOCKS];   // 16 KB
static __device__ unsigned int g_ctr  = 0;      // arrival counter (self-reset)
static __device__ unsigned int g_flag = 0;      // monotonic release flag

__device__ __forceinline__ float tanh_fast(float x) {
    float y;
    asm("tanh.approx.f32 %0, %1;" : "=f"(y) : "f"(x));
    return y;
}

__device__ __forceinline__ void accum1(float x, float m,
                                       float& sH, float& sHI, float& sI, float& sI2) {
    float h = fmaf(0.5f, tanh_fast(INV_EPISON * x), 0.5f);
    sH  += h;
    sHI  = fmaf(h, m, sHI);
    sI  += m;
    sI2  = fmaf(m, m, sI2);
}

__device__ __forceinline__ float4 ldcg4(const float4* p) {
    float4 v;
    asm volatile("ld.global.cg.v4.f32 {%0,%1,%2,%3}, [%4];"
                 : "=f"(v.x), "=f"(v.y), "=f"(v.z), "=f"(v.w) : "l"(p));
    return v;
}

__global__ void __launch_bounds__(THREADS, 8)
ls_loss_one(const float4* __restrict__ inp, const float4* __restrict__ img,
            float* __restrict__ out)
{
    const int b  = blockIdx.x;
    const int t  = threadIdx.x;
    const int ch = b >> 3;           // b / SUBS
    const int sub = b & 7;

    // Block 0 samples the release flag BEFORE doing anything else. The flag
    // can only flip after ALL 1024 arrivals (including block 0's own, which
    // happens after this read), so this read always sees the pre-flip value.
    unsigned int phase0 = 0;
    if (b == 0 && t == 0)
        asm volatile("ld.global.u32 %0, [%1];" : "=r"(phase0) : "l"(&g_flag));

    const long chbase = (long)ch * F4_PER_CH;

    float sH = 0.f, sHI = 0.f, sI = 0.f, sI2 = 0.f;

    #pragma unroll
    for (int k = 0; k < TILES_PER_BLK; k++) {
        const long tbase = chbase + (long)((sub + SUBS * k) * TILE_F4) + t;
        float4 x[GRP], m[GRP];
        #pragma unroll
        for (int j = 0; j < GRP; j++) {          // front-batch 8 LDG.128
            x[j] = __ldcs(&inp[tbase + j * THREADS]);
            m[j] = __ldcs(&img[tbase + j * THREADS]);
        }
        #pragma unroll
        for (int j = 0; j < GRP; j++) {
            accum1(x[j].x, m[j].x, sH, sHI, sI, sI2);
            accum1(x[j].y, m[j].y, sH, sHI, sI, sI2);
            accum1(x[j].z, m[j].z, sH, sHI, sI, sI2);
            accum1(x[j].w, m[j].w, sH, sHI, sI, sI2);
        }
    }

    // Deterministic warp tree reduce
    #pragma unroll
    for (int o = 16; o > 0; o >>= 1) {
        sH  += __shfl_down_sync(0xFFFFFFFFu, sH,  o);
        sHI += __shfl_down_sync(0xFFFFFFFFu, sHI, o);
        sI  += __shfl_down_sync(0xFFFFFFFFu, sI,  o);
        sI2 += __shfl_down_sync(0xFFFFFFFFu, sI2, o);
    }

    __shared__ float4 sm[THREADS / 32];
    const int warp = t >> 5, lane = t & 31;
    if (lane == 0) sm[warp] = make_float4(sH, sHI, sI, sI2);
    __syncthreads();

    if (t == 0) {
        float4 tot = sm[0];
        #pragma unroll
        for (int w = 1; w < THREADS / 32; w++) {
            float4 v = sm[w];
            tot.x += v.x; tot.y += v.y; tot.z += v.z; tot.w += v.w;
        }
        g_partials[b] = tot;
        __threadfence();                          // publish partial
        unsigned int prev = atomicAdd(&g_ctr, 1u);
        if (prev == NBLOCKS - 1) {
            // Last arriver: reset counter (everyone has arrived; nobody
            // reads it again this launch), then release block 0.
            *(volatile unsigned int*)&g_ctr = 0u;
            __threadfence();
            atomicAdd(&g_flag, 1u);               // monotonic flip
        }
    }

    if (b != 0) return;                           // non-zero blocks exit; no spin

    // ---- block 0: wait for all arrivals, then finalize everything ----
    if (t == 0) {
        unsigned int v;
        do {
            asm volatile("ld.global.acquire.gpu.u32 %0, [%1];"
                         : "=r"(v) : "l"(&g_flag));
            if (v == phase0) __nanosleep(64);
        } while (v == phase0);
    }
    __syncthreads();
    __threadfence();                              // order partial reads

    // thread t owns channel t: 8 partials, fixed order
    float A = 0.f, B1 = 0.f, S = 0.f, Q = 0.f;
    #pragma unroll
    for (int i = 0; i < SUBS; i++) {
        float4 v = ldcg4(&g_partials[t * SUBS + i]);
        A += v.x; B1 += v.y; S += v.z; Q += v.w;
    }

    const float Nf = (float)N_PER_CH;
    const float s3 = Nf - A;
    const float c1 = B1 / (A + LS_EPS);
    const float c2 = (S - B1) / (s3 + LS_EPS);
    float chan = Q - 2.f * (c1 * B1 + c2 * (S - B1))
               + c1 * c1 * A + c2 * c2 * s3;

    #pragma unroll
    for (int o = 16; o > 0; o >>= 1)
        chan += __shfl_down_sync(0xFFFFFFFFu, chan, o);

    __shared__ float smc[4];
    if (lane == 0) smc[warp] = chan;
    __syncthreads();

    if (t == 0) {
        out[0] = (smc[0] + smc[1] + smc[2] + smc[3])
               / (float)(32 * 4 * N_PER_CH);
    }
}

extern "C" void kernel_launch(void* const* d_in, const int* in_sizes, int n_in,
                              void* d_out, int out_size)
{
    const float4* inp = (const float4*)d_in[0];   // 'input'
    const float4* img = (const float4*)d_in[1];   // 'img_mean'
    ls_loss_one<<<NBLOCKS, THREADS>>>(inp, img, (float*)d_out);
}